// round 1
// baseline (speedup 1.0000x reference)
#include <cuda_runtime.h>

// Problem constants
#define BB   64
#define TT   512
#define HH   1024
#define CC   8
#define NSEQ 192           // 3 tasks * 64 batch
#define NROW 32768         // BB*TT
#define LOGITS_OFF 1
#define PRED_OFF   (1 + 3*BB*TT*CC)   // 1 + 786432

// ---------------------------------------------------------------------------
// Kernel 1: logits[k,b,t,c] = enc[b,t,:] . W[k,c,:] + bias[k,c]
// M=32768 rows (b*T+t), N=24 cols (k*8+c), K=1024.
// Tile: 128 rows x 24 cols x 32 K-chunk, 256 threads, 4x3 register block.
// Also initializes out[0] (loss accumulator) to 0.
// ---------------------------------------------------------------------------
__global__ __launch_bounds__(256) void gemm_kernel(
    const float* __restrict__ enc, const float* __restrict__ W,
    const float* __restrict__ bias, float* __restrict__ out)
{
    __shared__ float As[128][33];   // [row][k], +1 pad -> conflict-free lane reads
    __shared__ float Ws[24][33];

    const int tid  = threadIdx.x;
    const int rb   = blockIdx.x * 128;
    const int rgrp = tid & 31;          // lane -> row group (stride-32 rows)
    const int c0   = (tid >> 5) * 3;    // warp -> 3 output cols

    if (blockIdx.x == 0 && tid == 0) out[0] = 0.0f;  // loss init (kernel 2 atomics come later in-stream)

    float acc[4][3] = {};

    for (int kb = 0; kb < HH; kb += 32) {
        // Load A tile: 128 rows x 32 k = 1024 float4
        #pragma unroll
        for (int i = 0; i < 4; i++) {
            int idx = tid + i * 256;
            int row = idx >> 3, kq = idx & 7;
            float4 v = *reinterpret_cast<const float4*>(
                &enc[(rb + row) * HH + kb + kq * 4]);
            As[row][kq * 4 + 0] = v.x;
            As[row][kq * 4 + 1] = v.y;
            As[row][kq * 4 + 2] = v.z;
            As[row][kq * 4 + 3] = v.w;
        }
        // Load W tile: 24 x 32
        for (int idx = tid; idx < 768; idx += 256) {
            int c = idx >> 5, k = idx & 31;
            Ws[c][k] = W[c * HH + kb + k];
        }
        __syncthreads();

        #pragma unroll
        for (int k = 0; k < 32; k++) {
            float a0 = As[rgrp      ][k];
            float a1 = As[rgrp + 32 ][k];
            float a2 = As[rgrp + 64 ][k];
            float a3 = As[rgrp + 96 ][k];
            float w0 = Ws[c0    ][k];
            float w1 = Ws[c0 + 1][k];
            float w2 = Ws[c0 + 2][k];
            acc[0][0] += a0 * w0; acc[0][1] += a0 * w1; acc[0][2] += a0 * w2;
            acc[1][0] += a1 * w0; acc[1][1] += a1 * w1; acc[1][2] += a1 * w2;
            acc[2][0] += a2 * w0; acc[2][1] += a2 * w1; acc[2][2] += a2 * w2;
            acc[3][0] += a3 * w0; acc[3][1] += a3 * w1; acc[3][2] += a3 * w2;
        }
        __syncthreads();
    }

    // Epilogue: out layout logits[k][b][t][c] starting at out[1]
    #pragma unroll
    for (int i = 0; i < 4; i++) {
        int r = rb + rgrp + 32 * i;
        #pragma unroll
        for (int jj = 0; jj < 3; jj++) {
            int col = c0 + jj;
            int kt = col >> 3, c = col & 7;
            out[LOGITS_OFF + (kt * NROW + r) * CC + c] = acc[i][jj] + bias[col];
        }
    }
}

// ---------------------------------------------------------------------------
// Kernel 2 (combined, block-specialized):
//   blocks 0..11 : Viterbi, 16 sequences/block, 8 lanes per sequence
//   blocks 12..17: CRF forward + numerator, 16 groups/block, 2 seqs per group
// Both read logits from out[1..], write pred / atomicAdd loss.
// ---------------------------------------------------------------------------
__global__ __launch_bounds__(128) void crf_kernel(
    const int* __restrict__ labels, const float* __restrict__ start_t,
    const float* __restrict__ end_t, const float* __restrict__ trans,
    float* __restrict__ out)
{
    __shared__ unsigned int  bpS[16][512];   // packed backpointers (8 states x 3 bits)
    __shared__ unsigned char tagb[16][512];  // decoded tags

    const unsigned FULL = 0xFFFFFFFFu;
    const int tid = threadIdx.x;
    const int j   = tid & 7;       // state lane within group
    const int lg  = tid >> 3;      // local group 0..15
    const float* lgt = out + LOGITS_OFF;

    if (blockIdx.x < 12) {
        // ------------------------- Viterbi -------------------------
        int s = blockIdx.x * 16 + lg;           // sequence 0..191
        int k = s >> 6, b = s & 63;
        const float* em = lgt + (k * 64 + b) * (TT * CC);

        float trcol[8];
        #pragma unroll
        for (int i = 0; i < 8; i++) trcol[i] = trans[k * 64 + i * 8 + j];

        float v = start_t[k * 8 + j] + em[j];
        float e = em[8 + j];

        for (int t = 1; t < TT; t++) {
            float en = (t < TT - 1) ? em[(t + 1) * 8 + j] : 0.0f;
            // gather prev scores, score candidates
            float sc[8];
            #pragma unroll
            for (int i = 0; i < 8; i++)
                sc[i] = __shfl_sync(FULL, v, i, 8) + trcol[i];
            // max tree
            float m01 = fmaxf(sc[0], sc[1]), m23 = fmaxf(sc[2], sc[3]);
            float m45 = fmaxf(sc[4], sc[5]), m67 = fmaxf(sc[6], sc[7]);
            float best = fmaxf(fmaxf(m01, m23), fmaxf(m45, m67));
            // first index achieving max (matches jnp.argmax tie-break)
            unsigned mk = 0;
            #pragma unroll
            for (int i = 0; i < 8; i++) mk |= (sc[i] == best) ? (1u << i) : 0u;
            int bi = __ffs(mk) - 1;
            v = best + e;
            // pack backpointers into one word per t
            unsigned w = ((unsigned)bi) << (3 * j);
            #pragma unroll
            for (int d = 4; d > 0; d >>= 1) w |= __shfl_xor_sync(FULL, w, d, 8);
            if (j == 0) bpS[lg][t] = w;
            e = en;
        }

        // final argmax over states (first-occurrence tie-break)
        float y = v + end_t[k * 8 + j];
        float g[8];
        #pragma unroll
        for (int i = 0; i < 8; i++) g[i] = __shfl_sync(FULL, y, i, 8);
        float bv = g[0]; int last = 0;
        #pragma unroll
        for (int i = 1; i < 8; i++) { if (g[i] > bv) { bv = g[i]; last = i; } }

        __syncwarp();
        if (j == 0) {
            int tag = last;
            tagb[lg][TT - 1] = (unsigned char)tag;
            for (int t = TT - 2; t >= 0; t--) {
                unsigned w = bpS[lg][t + 1];
                tag = (w >> (3 * tag)) & 7;
                tagb[lg][t] = (unsigned char)tag;
            }
        }
        __syncwarp();

        float* pred = out + PRED_OFF;
        int pb = (k * 64 + b) * TT;
        for (int t = j; t < TT; t += 8)
            pred[pb + t] = (float)tagb[lg][t];
    } else {
        // ------------------ CRF forward + numerator ------------------
        int grp = (blockIdx.x - 12) * 16 + lg;   // 0..95, each handles 2 seqs
        int s0 = grp * 2, s1 = grp * 2 + 1;
        int k0 = s0 >> 6, b0 = s0 & 63;
        int k1 = s1 >> 6, b1 = s1 & 63;
        const float* em0 = lgt + (k0 * 64 + b0) * (TT * CC);
        const float* em1 = lgt + (k1 * 64 + b1) * (TT * CC);

        float ec0[8], ec1[8];
        #pragma unroll
        for (int i = 0; i < 8; i++) {
            ec0[i] = __expf(trans[k0 * 64 + i * 8 + j]);
            ec1[i] = __expf(trans[k1 * 64 + i * 8 + j]);
        }

        float z0 = start_t[k0 * 8 + j] + em0[j];
        float z1 = start_t[k1 * 8 + j] + em1[j];
        float C0 = 0.0f, C1 = 0.0f;
        float e0 = em0[8 + j], e1 = em1[8 + j];

        for (int t = 1; t < TT; t++) {
            float en0 = (t < TT - 1) ? em0[(t + 1) * 8 + j] : 0.0f;
            float en1 = (t < TT - 1) ? em1[(t + 1) * 8 + j] : 0.0f;
            // renorm by lane-0 state (bounded spread => safe)
            float m0 = __shfl_sync(FULL, z0, 0, 8);
            float m1 = __shfl_sync(FULL, z1, 0, 8);
            float p0 = __expf(z0 - m0);
            float p1 = __expf(z1 - m1);
            float sA = 0.0f, sB = 0.0f;
            #pragma unroll
            for (int i = 0; i < 8; i++) {
                sA += __shfl_sync(FULL, p0, i, 8) * ec0[i];
                sB += __shfl_sync(FULL, p1, i, 8) * ec1[i];
            }
            z0 = __logf(sA) + e0;
            z1 = __logf(sB) + e1;
            C0 += m0; C1 += m1;
            e0 = en0; e1 = en1;
        }

        // logZ = LSE_j(z + end) + C
        float y0 = z0 + end_t[k0 * 8 + j];
        float y1 = z1 + end_t[k1 * 8 + j];
        float mm0 = y0, mm1 = y1;
        #pragma unroll
        for (int d = 4; d > 0; d >>= 1) {
            mm0 = fmaxf(mm0, __shfl_xor_sync(FULL, mm0, d, 8));
            mm1 = fmaxf(mm1, __shfl_xor_sync(FULL, mm1, d, 8));
        }
        float q0 = __expf(y0 - mm0), q1 = __expf(y1 - mm1);
        #pragma unroll
        for (int d = 4; d > 0; d >>= 1) {
            q0 += __shfl_xor_sync(FULL, q0, d, 8);
            q1 += __shfl_xor_sync(FULL, q1, d, 8);
        }
        float logZ0 = __logf(q0) + mm0 + C0;
        float logZ1 = __logf(q1) + mm1 + C1;

        // numerator (gold path score), lanes stride T
        float num0 = 0.0f, num1 = 0.0f;
        for (int t = j; t < TT; t += 8) {
            int tg0 = labels[b0 * (3 * TT) + k0 * TT + t];
            num0 += em0[t * 8 + tg0];
            if (t > 0) {
                int tp = labels[b0 * (3 * TT) + k0 * TT + t - 1];
                num0 += trans[k0 * 64 + tp * 8 + tg0];
            } else {
                num0 += start_t[k0 * 8 + tg0];
            }
            if (t == TT - 1) num0 += end_t[k0 * 8 + tg0];

            int tg1 = labels[b1 * (3 * TT) + k1 * TT + t];
            num1 += em1[t * 8 + tg1];
            if (t > 0) {
                int tp = labels[b1 * (3 * TT) + k1 * TT + t - 1];
                num1 += trans[k1 * 64 + tp * 8 + tg1];
            } else {
                num1 += start_t[k1 * 8 + tg1];
            }
            if (t == TT - 1) num1 += end_t[k1 * 8 + tg1];
        }
        #pragma unroll
        for (int d = 4; d > 0; d >>= 1) {
            num0 += __shfl_xor_sync(FULL, num0, d, 8);
            num1 += __shfl_xor_sync(FULL, num1, d, 8);
        }

        if (j == 0)
            atomicAdd(&out[0], (logZ0 - num0) + (logZ1 - num1));
    }
}

// ---------------------------------------------------------------------------
extern "C" void kernel_launch(void* const* d_in, const int* in_sizes, int n_in,
                              void* d_out, int out_size)
{
    (void)in_sizes; (void)n_in; (void)out_size;
    const float* enc     = (const float*)d_in[0];
    const int*   labels  = (const int*)  d_in[1];
    const float* W       = (const float*)d_in[2];
    const float* bias    = (const float*)d_in[3];
    const float* start_t = (const float*)d_in[4];
    const float* end_t   = (const float*)d_in[5];
    const float* trans   = (const float*)d_in[6];
    float* out = (float*)d_out;

    gemm_kernel<<<NROW / 128, 256>>>(enc, W, bias, out);
    crf_kernel<<<18, 128>>>(labels, start_t, end_t, trans, out);
}

// round 2
// speedup vs baseline: 1.0014x; 1.0014x over previous
#include <cuda_runtime.h>

// Problem constants
#define BB   64
#define TT   512
#define HH   1024
#define CC   8
#define NSEQ 192           // 3 tasks * 64 batch
#define NROW 32768         // BB*TT
#define LOGITS_OFF 1
#define PRED_OFF   (1 + 3*BB*TT*CC)   // 1 + 786432

// ---------------------------------------------------------------------------
// Kernel 1: logits[k,b,t,c] = enc[b,t,:] . W[k,c,:] + bias[k,c]
// M=32768 rows (b*T+t), N=24 cols (k*8+c), K=1024.
// Tile: 128 rows x 24 cols x 32 K-chunk, 256 threads, 4x3 register block.
// Also initializes out[0] (loss accumulator) to 0.
// ---------------------------------------------------------------------------
__global__ __launch_bounds__(256) void gemm_kernel(
    const float* __restrict__ enc, const float* __restrict__ W,
    const float* __restrict__ bias, float* __restrict__ out)
{
    __shared__ float As[128][33];   // [row][k], +1 pad -> conflict-free lane reads
    __shared__ float Ws[24][33];

    const int tid  = threadIdx.x;
    const int rb   = blockIdx.x * 128;
    const int rgrp = tid & 31;          // lane -> row group (stride-32 rows)
    const int c0   = (tid >> 5) * 3;    // warp -> 3 output cols

    if (blockIdx.x == 0 && tid == 0) out[0] = 0.0f;  // loss init (kernel 2 atomics come later in-stream)

    float acc[4][3] = {};

    for (int kb = 0; kb < HH; kb += 32) {
        // Load A tile: 128 rows x 32 k = 1024 float4
        #pragma unroll
        for (int i = 0; i < 4; i++) {
            int idx = tid + i * 256;
            int row = idx >> 3, kq = idx & 7;
            float4 v = *reinterpret_cast<const float4*>(
                &enc[(rb + row) * HH + kb + kq * 4]);
            As[row][kq * 4 + 0] = v.x;
            As[row][kq * 4 + 1] = v.y;
            As[row][kq * 4 + 2] = v.z;
            As[row][kq * 4 + 3] = v.w;
        }
        // Load W tile: 24 x 32
        for (int idx = tid; idx < 768; idx += 256) {
            int c = idx >> 5, k = idx & 31;
            Ws[c][k] = W[c * HH + kb + k];
        }
        __syncthreads();

        #pragma unroll
        for (int k = 0; k < 32; k++) {
            float a0 = As[rgrp      ][k];
            float a1 = As[rgrp + 32 ][k];
            float a2 = As[rgrp + 64 ][k];
            float a3 = As[rgrp + 96 ][k];
            float w0 = Ws[c0    ][k];
            float w1 = Ws[c0 + 1][k];
            float w2 = Ws[c0 + 2][k];
            acc[0][0] += a0 * w0; acc[0][1] += a0 * w1; acc[0][2] += a0 * w2;
            acc[1][0] += a1 * w0; acc[1][1] += a1 * w1; acc[1][2] += a1 * w2;
            acc[2][0] += a2 * w0; acc[2][1] += a2 * w1; acc[2][2] += a2 * w2;
            acc[3][0] += a3 * w0; acc[3][1] += a3 * w1; acc[3][2] += a3 * w2;
        }
        __syncthreads();
    }

    // Epilogue: out layout logits[k][b][t][c] starting at out[1]
    #pragma unroll
    for (int i = 0; i < 4; i++) {
        int r = rb + rgrp + 32 * i;
        #pragma unroll
        for (int jj = 0; jj < 3; jj++) {
            int col = c0 + jj;
            int kt = col >> 3, c = col & 7;
            out[LOGITS_OFF + (kt * NROW + r) * CC + c] = acc[i][jj] + bias[col];
        }
    }
}

// ---------------------------------------------------------------------------
// Kernel 2 (combined, block-specialized):
//   blocks 0..11 : Viterbi, 16 sequences/block, 8 lanes per sequence
//   blocks 12..17: CRF forward + numerator, 16 groups/block, 2 seqs per group
// Both read logits from out[1..], write pred / atomicAdd loss.
// ---------------------------------------------------------------------------
__global__ __launch_bounds__(128) void crf_kernel(
    const int* __restrict__ labels, const float* __restrict__ start_t,
    const float* __restrict__ end_t, const float* __restrict__ trans,
    float* __restrict__ out)
{
    __shared__ unsigned int  bpS[16][512];   // packed backpointers (8 states x 3 bits)
    __shared__ unsigned char tagb[16][512];  // decoded tags

    const unsigned FULL = 0xFFFFFFFFu;
    const int tid = threadIdx.x;
    const int j   = tid & 7;       // state lane within group
    const int lg  = tid >> 3;      // local group 0..15
    const float* lgt = out + LOGITS_OFF;

    if (blockIdx.x < 12) {
        // ------------------------- Viterbi -------------------------
        int s = blockIdx.x * 16 + lg;           // sequence 0..191
        int k = s >> 6, b = s & 63;
        const float* em = lgt + (k * 64 + b) * (TT * CC);

        float trcol[8];
        #pragma unroll
        for (int i = 0; i < 8; i++) trcol[i] = trans[k * 64 + i * 8 + j];

        float v = start_t[k * 8 + j] + em[j];
        float e = em[8 + j];

        for (int t = 1; t < TT; t++) {
            float en = (t < TT - 1) ? em[(t + 1) * 8 + j] : 0.0f;
            // gather prev scores, score candidates
            float sc[8];
            #pragma unroll
            for (int i = 0; i < 8; i++)
                sc[i] = __shfl_sync(FULL, v, i, 8) + trcol[i];
            // max tree
            float m01 = fmaxf(sc[0], sc[1]), m23 = fmaxf(sc[2], sc[3]);
            float m45 = fmaxf(sc[4], sc[5]), m67 = fmaxf(sc[6], sc[7]);
            float best = fmaxf(fmaxf(m01, m23), fmaxf(m45, m67));
            // first index achieving max (matches jnp.argmax tie-break)
            unsigned mk = 0;
            #pragma unroll
            for (int i = 0; i < 8; i++) mk |= (sc[i] == best) ? (1u << i) : 0u;
            int bi = __ffs(mk) - 1;
            v = best + e;
            // pack backpointers into one word per t
            unsigned w = ((unsigned)bi) << (3 * j);
            #pragma unroll
            for (int d = 4; d > 0; d >>= 1) w |= __shfl_xor_sync(FULL, w, d, 8);
            if (j == 0) bpS[lg][t] = w;
            e = en;
        }

        // final argmax over states (first-occurrence tie-break)
        float y = v + end_t[k * 8 + j];
        float g[8];
        #pragma unroll
        for (int i = 0; i < 8; i++) g[i] = __shfl_sync(FULL, y, i, 8);
        float bv = g[0]; int last = 0;
        #pragma unroll
        for (int i = 1; i < 8; i++) { if (g[i] > bv) { bv = g[i]; last = i; } }

        __syncwarp();
        if (j == 0) {
            int tag = last;
            tagb[lg][TT - 1] = (unsigned char)tag;
            for (int t = TT - 2; t >= 0; t--) {
                unsigned w = bpS[lg][t + 1];
                tag = (w >> (3 * tag)) & 7;
                tagb[lg][t] = (unsigned char)tag;
            }
        }
        __syncwarp();

        float* pred = out + PRED_OFF;
        int pb = (k * 64 + b) * TT;
        for (int t = j; t < TT; t += 8)
            pred[pb + t] = (float)tagb[lg][t];
    } else {
        // ------------------ CRF forward + numerator ------------------
        int grp = (blockIdx.x - 12) * 16 + lg;   // 0..95, each handles 2 seqs
        int s0 = grp * 2, s1 = grp * 2 + 1;
        int k0 = s0 >> 6, b0 = s0 & 63;
        int k1 = s1 >> 6, b1 = s1 & 63;
        const float* em0 = lgt + (k0 * 64 + b0) * (TT * CC);
        const float* em1 = lgt + (k1 * 64 + b1) * (TT * CC);

        float ec0[8], ec1[8];
        #pragma unroll
        for (int i = 0; i < 8; i++) {
            ec0[i] = __expf(trans[k0 * 64 + i * 8 + j]);
            ec1[i] = __expf(trans[k1 * 64 + i * 8 + j]);
        }

        float z0 = start_t[k0 * 8 + j] + em0[j];
        float z1 = start_t[k1 * 8 + j] + em1[j];
        float C0 = 0.0f, C1 = 0.0f;
        float e0 = em0[8 + j], e1 = em1[8 + j];

        for (int t = 1; t < TT; t++) {
            float en0 = (t < TT - 1) ? em0[(t + 1) * 8 + j] : 0.0f;
            float en1 = (t < TT - 1) ? em1[(t + 1) * 8 + j] : 0.0f;
            // renorm by lane-0 state (bounded spread => safe)
            float m0 = __shfl_sync(FULL, z0, 0, 8);
            float m1 = __shfl_sync(FULL, z1, 0, 8);
            float p0 = __expf(z0 - m0);
            float p1 = __expf(z1 - m1);
            float sA = 0.0f, sB = 0.0f;
            #pragma unroll
            for (int i = 0; i < 8; i++) {
                sA += __shfl_sync(FULL, p0, i, 8) * ec0[i];
                sB += __shfl_sync(FULL, p1, i, 8) * ec1[i];
            }
            z0 = __logf(sA) + e0;
            z1 = __logf(sB) + e1;
            C0 += m0; C1 += m1;
            e0 = en0; e1 = en1;
        }

        // logZ = LSE_j(z + end) + C
        float y0 = z0 + end_t[k0 * 8 + j];
        float y1 = z1 + end_t[k1 * 8 + j];
        float mm0 = y0, mm1 = y1;
        #pragma unroll
        for (int d = 4; d > 0; d >>= 1) {
            mm0 = fmaxf(mm0, __shfl_xor_sync(FULL, mm0, d, 8));
            mm1 = fmaxf(mm1, __shfl_xor_sync(FULL, mm1, d, 8));
        }
        float q0 = __expf(y0 - mm0), q1 = __expf(y1 - mm1);
        #pragma unroll
        for (int d = 4; d > 0; d >>= 1) {
            q0 += __shfl_xor_sync(FULL, q0, d, 8);
            q1 += __shfl_xor_sync(FULL, q1, d, 8);
        }
        float logZ0 = __logf(q0) + mm0 + C0;
        float logZ1 = __logf(q1) + mm1 + C1;

        // numerator (gold path score), lanes stride T
        float num0 = 0.0f, num1 = 0.0f;
        for (int t = j; t < TT; t += 8) {
            int tg0 = labels[b0 * (3 * TT) + k0 * TT + t];
            num0 += em0[t * 8 + tg0];
            if (t > 0) {
                int tp = labels[b0 * (3 * TT) + k0 * TT + t - 1];
                num0 += trans[k0 * 64 + tp * 8 + tg0];
            } else {
                num0 += start_t[k0 * 8 + tg0];
            }
            if (t == TT - 1) num0 += end_t[k0 * 8 + tg0];

            int tg1 = labels[b1 * (3 * TT) + k1 * TT + t];
            num1 += em1[t * 8 + tg1];
            if (t > 0) {
                int tp = labels[b1 * (3 * TT) + k1 * TT + t - 1];
                num1 += trans[k1 * 64 + tp * 8 + tg1];
            } else {
                num1 += start_t[k1 * 8 + tg1];
            }
            if (t == TT - 1) num1 += end_t[k1 * 8 + tg1];
        }
        #pragma unroll
        for (int d = 4; d > 0; d >>= 1) {
            num0 += __shfl_xor_sync(FULL, num0, d, 8);
            num1 += __shfl_xor_sync(FULL, num1, d, 8);
        }

        if (j == 0)
            atomicAdd(&out[0], (logZ0 - num0) + (logZ1 - num1));
    }
}

// ---------------------------------------------------------------------------
extern "C" void kernel_launch(void* const* d_in, const int* in_sizes, int n_in,
                              void* d_out, int out_size)
{
    (void)in_sizes; (void)n_in; (void)out_size;
    const float* enc     = (const float*)d_in[0];
    const int*   labels  = (const int*)  d_in[1];
    const float* W       = (const float*)d_in[2];
    const float* bias    = (const float*)d_in[3];
    const float* start_t = (const float*)d_in[4];
    const float* end_t   = (const float*)d_in[5];
    const float* trans   = (const float*)d_in[6];
    float* out = (float*)d_out;

    gemm_kernel<<<NROW / 128, 256>>>(enc, W, bias, out);
    crf_kernel<<<18, 128>>>(labels, start_t, end_t, trans, out);
}

// round 3
// speedup vs baseline: 1.3823x; 1.3803x over previous
#include <cuda_runtime.h>

#define BB   64
#define TT   512
#define HH   1024
#define CC   8
#define NROW 32768
#define LOGITS_OFF 1
#define PRED_OFF   (1 + 3*BB*TT*CC)
#define FULLM 0xFFFFFFFFu

// device scratch (static: no allocations allowed)
__device__ float    g_expo[3 * NROW * CC];   // exp(logits)
__device__ float    g_vscr[192 * TT * CC];   // viterbi v_t
__device__ float    g_fwdP[192 * 8 * 64];    // forward chunk basis matrices
__device__ unsigned g_bpw [192 * TT];        // packed backpointers

__device__ __forceinline__ void ffma2(unsigned long long& d,
                                      unsigned long long a,
                                      unsigned long long b) {
    asm("fma.rn.f32x2 %0, %1, %2, %0;" : "+l"(d) : "l"(a), "l"(b));
}
__device__ __forceinline__ void cpa16(unsigned sm, const void* g) {
    asm volatile("cp.async.cg.shared.global [%0], [%1], 16;" :: "r"(sm), "l"(g));
}

// ---------------------------------------------------------------------------
// GEMM: M=32768, N=24, K=1024. 128 thr/block, 2 rows/thread (tid, tid+128),
// 256 rows/block, 128 blocks. f32x2 FMA, cp.async double-buffered k16 tiles.
// Writes logits to out[1..] and exp(logits) to g_expo.
// ---------------------------------------------------------------------------
__global__ __launch_bounds__(128) void gemm_kernel(
    const float* __restrict__ enc, const float* __restrict__ W,
    const float* __restrict__ bias, float* __restrict__ out)
{
    __shared__ float As[2][256 * 20];
    __shared__ float Ws[2][24 * 20];

    const int tid = threadIdx.x;
    const int rb  = blockIdx.x * 256;
    if (blockIdx.x == 0 && tid == 0) out[0] = 0.0f;

    unsigned long long acc0[24], acc1[24];
    #pragma unroll
    for (int c = 0; c < 24; c++) { acc0[c] = 0ull; acc1[c] = 0ull; }

    unsigned asB[2] = { (unsigned)__cvta_generic_to_shared(&As[0][0]),
                        (unsigned)__cvta_generic_to_shared(&As[1][0]) };
    unsigned wsB[2] = { (unsigned)__cvta_generic_to_shared(&Ws[0][0]),
                        (unsigned)__cvta_generic_to_shared(&Ws[1][0]) };

    auto load_tiles = [&](int kb, int bf) {
        #pragma unroll
        for (int i = 0; i < 8; i++) {
            int idx = tid + i * 128;
            int row = idx >> 2, q = idx & 3;
            cpa16(asB[bf] + (row * 20 + q * 4) * 4,
                  enc + (size_t)(rb + row) * HH + kb + q * 4);
        }
        if (tid < 96) {
            int c = tid >> 2, q = tid & 3;
            cpa16(wsB[bf] + (c * 20 + q * 4) * 4, W + (size_t)c * HH + kb + q * 4);
        }
        asm volatile("cp.async.commit_group;");
    };

    load_tiles(0, 0);
    int buf = 0;
    for (int kb = 0; kb < HH; kb += 16, buf ^= 1) {
        if (kb + 16 < HH) {
            load_tiles(kb + 16, buf ^ 1);
            asm volatile("cp.async.wait_group 1;");
        } else {
            asm volatile("cp.async.wait_group 0;");
        }
        __syncthreads();
        const float* A0 = &As[buf][tid * 20];
        const float* A1 = &As[buf][(tid + 128) * 20];
        #pragma unroll
        for (int k4 = 0; k4 < 16; k4 += 4) {
            ulonglong2 a0 = *reinterpret_cast<const ulonglong2*>(&A0[k4]);
            ulonglong2 a1 = *reinterpret_cast<const ulonglong2*>(&A1[k4]);
            #pragma unroll
            for (int c = 0; c < 24; c++) {
                ulonglong2 wp = *reinterpret_cast<const ulonglong2*>(&Ws[buf][c * 20 + k4]);
                ffma2(acc0[c], a0.x, wp.x);
                ffma2(acc0[c], a0.y, wp.y);
                ffma2(acc1[c], a1.x, wp.x);
                ffma2(acc1[c], a1.y, wp.y);
            }
        }
        __syncthreads();
    }

    #pragma unroll
    for (int half = 0; half < 2; half++) {
        const int r = rb + tid + half * 128;
        unsigned long long* acc = half ? acc1 : acc0;
        #pragma unroll
        for (int kt = 0; kt < 3; kt++) {
            float res[8];
            #pragma unroll
            for (int cc = 0; cc < 8; cc++) {
                float2 f = *reinterpret_cast<float2*>(&acc[kt * 8 + cc]);
                res[cc] = f.x + f.y + bias[kt * 8 + cc];
            }
            size_t base = ((size_t)kt * NROW + r) * 8;
            #pragma unroll
            for (int cc = 0; cc < 8; cc++) out[LOGITS_OFF + base + cc] = res[cc];
            float4 e0 = { __expf(res[0]), __expf(res[1]), __expf(res[2]), __expf(res[3]) };
            float4 e1 = { __expf(res[4]), __expf(res[5]), __expf(res[6]), __expf(res[7]) };
            *reinterpret_cast<float4*>(&g_expo[base])     = e0;
            *reinterpret_cast<float4*>(&g_expo[base + 4]) = e1;
        }
    }
}

// ---------------------------------------------------------------------------
// scan: blocks 0..11 = exact Viterbi v-scan (stores all v_t)
//       blocks 12..107 = forward chunk basis matrices (linear domain)
// ---------------------------------------------------------------------------
__global__ __launch_bounds__(128) void scan_kernel(
    const float* __restrict__ start_t, const float* __restrict__ trans,
    const float* __restrict__ out)
{
    const int tid = threadIdx.x;

    if (blockIdx.x < 12) {
        const int g  = blockIdx.x * 16 + (tid >> 3);
        const int j  = tid & 7;
        const int kt = g >> 6;
        const float* em = out + LOGITS_OFF + (size_t)g * (TT * CC);
        float* vs = g_vscr + (size_t)g * (TT * CC);

        float tr[8];
        #pragma unroll
        for (int i = 0; i < 8; i++) tr[i] = trans[kt * 64 + i * 8 + j];

        float v = start_t[kt * 8 + j] + em[j];
        vs[j] = v;

        float eb[8];
        #pragma unroll
        for (int u = 0; u < 8; u++) eb[u] = em[(1 + u) * 8 + j];

        for (int tw = 1; tw < TT; tw += 8) {
            float nb[8];
            #pragma unroll
            for (int u = 0; u < 8; u++) {
                int tn = tw + 8 + u;
                nb[u] = (tn < TT) ? em[tn * 8 + j] : 0.0f;
            }
            #pragma unroll
            for (int u = 0; u < 8; u++) {
                int t = tw + u;
                if (t < TT) {
                    float c0 = __shfl_sync(FULLM, v, 0, 8) + tr[0];
                    float c1 = __shfl_sync(FULLM, v, 1, 8) + tr[1];
                    float c2 = __shfl_sync(FULLM, v, 2, 8) + tr[2];
                    float c3 = __shfl_sync(FULLM, v, 3, 8) + tr[3];
                    float c4 = __shfl_sync(FULLM, v, 4, 8) + tr[4];
                    float c5 = __shfl_sync(FULLM, v, 5, 8) + tr[5];
                    float c6 = __shfl_sync(FULLM, v, 6, 8) + tr[6];
                    float c7 = __shfl_sync(FULLM, v, 7, 8) + tr[7];
                    float m = fmaxf(fmaxf(fmaxf(c0, c1), fmaxf(c2, c3)),
                                    fmaxf(fmaxf(c4, c5), fmaxf(c6, c7)));
                    v = m + eb[u];
                    vs[t * 8 + j] = v;
                }
            }
            #pragma unroll
            for (int u = 0; u < 8; u++) eb[u] = nb[u];
        }
    } else {
        // thread = (seq s, chunk c, basis row ib)
        const int flat = (blockIdx.x - 12) * 128 + tid;
        const int ib = flat & 7;
        const int c  = (flat >> 3) & 7;
        const int s  = flat >> 6;
        const int kt = s >> 6;

        float ec[64];
        #pragma unroll
        for (int i = 0; i < 64; i++) ec[i] = __expf(trans[kt * 64 + i]) * 0.125f;

        float P[8];
        #pragma unroll
        for (int jj = 0; jj < 8; jj++) P[jj] = (jj == ib) ? 1.0f : 0.0f;

        const int tb = c * 64 + 1;
        const int te = (c * 64 + 64 < TT) ? c * 64 + 64 : TT - 1;
        const float* eo = g_expo + (size_t)s * (TT * CC);

        float4 pa0 = *reinterpret_cast<const float4*>(eo + tb * 8);
        float4 pb0 = *reinterpret_cast<const float4*>(eo + tb * 8 + 4);
        float4 pa1 = *reinterpret_cast<const float4*>(eo + (tb + 1) * 8);
        float4 pb1 = *reinterpret_cast<const float4*>(eo + (tb + 1) * 8 + 4);

        for (int t = tb; t <= te; t++) {
            float4 ca = pa0, cb = pb0;
            pa0 = pa1; pb0 = pb1;
            int tn = t + 2;
            if (tn <= te) {
                pa1 = *reinterpret_cast<const float4*>(eo + tn * 8);
                pb1 = *reinterpret_cast<const float4*>(eo + tn * 8 + 4);
            }
            float np[8];
            #pragma unroll
            for (int jj = 0; jj < 8; jj++) {
                float sum = P[0] * ec[jj];
                #pragma unroll
                for (int i = 1; i < 8; i++) sum = fmaf(P[i], ec[i * 8 + jj], sum);
                np[jj] = sum;
            }
            P[0] = np[0] * ca.x; P[1] = np[1] * ca.y;
            P[2] = np[2] * ca.z; P[3] = np[3] * ca.w;
            P[4] = np[4] * cb.x; P[5] = np[5] * cb.y;
            P[6] = np[6] * cb.z; P[7] = np[7] * cb.w;
        }
        float* dst = g_fwdP + ((size_t)(s * 8 + c) * 8 + ib) * 8;
        *reinterpret_cast<float4*>(dst)     = make_float4(P[0], P[1], P[2], P[3]);
        *reinterpret_cast<float4*>(dst + 4) = make_float4(P[4], P[5], P[6], P[7]);
    }
}

// ---------------------------------------------------------------------------
// post: blocks 0..383 = backpointers (parallel over s,t)
//       blocks 384..389 = logZ combine + numerator + loss
// ---------------------------------------------------------------------------
__global__ __launch_bounds__(256) void post_kernel(
    const int* __restrict__ labels, const float* __restrict__ start_t,
    const float* __restrict__ end_t, const float* __restrict__ trans,
    float* __restrict__ out)
{
    const int tid = threadIdx.x;

    if (blockIdx.x < 384) {
        __shared__ float str[192];
        if (tid < 192) str[tid] = trans[tid];
        __syncthreads();

        const int id = blockIdx.x * 256 + tid;    // s*512 + t
        const int t  = id & 511;
        if (t == 0) return;
        const int s  = id >> 9;
        const int kt = s >> 6;

        const float4* vp = reinterpret_cast<const float4*>(
            g_vscr + ((size_t)s * TT + (t - 1)) * 8);
        float4 va = vp[0], vb = vp[1];
        float v[8] = { va.x, va.y, va.z, va.w, vb.x, vb.y, vb.z, vb.w };

        unsigned word = 0;
        #pragma unroll
        for (int j = 0; j < 8; j++) {
            float best = v[0] + str[kt * 64 + j];
            int bi = 0;
            #pragma unroll
            for (int i = 1; i < 8; i++) {
                float cnd = v[i] + str[kt * 64 + i * 8 + j];
                if (cnd > best) { best = cnd; bi = i; }
            }
            word |= (unsigned)bi << (3 * j);
        }
        g_bpw[id] = word;
    } else {
        const int g  = (blockIdx.x - 384) * 32 + (tid >> 3);   // seq 0..191
        const int j  = tid & 7;
        const int kt = g >> 6, b = g & 63;
        const float* em = out + LOGITS_OFF + (size_t)g * (TT * CC);
        const float LOG8 = 2.0794415416798357f;

        float a = start_t[kt * 8 + j] + em[j];
        for (int c = 0; c < 8; c++) {
            float n = (c < 7) ? 64.0f : 63.0f;
            const float* Pp = g_fwdP + (size_t)(g * 8 + c) * 64;
            float lm[8];
            #pragma unroll
            for (int i = 0; i < 8; i++)
                lm[i] = __logf(Pp[i * 8 + j]) + n * LOG8 + __shfl_sync(FULLM, a, i, 8);
            float m = fmaxf(fmaxf(fmaxf(lm[0], lm[1]), fmaxf(lm[2], lm[3])),
                            fmaxf(fmaxf(lm[4], lm[5]), fmaxf(lm[6], lm[7])));
            float ssum = 0.0f;
            #pragma unroll
            for (int i = 0; i < 8; i++) ssum += __expf(lm[i] - m);
            a = m + __logf(ssum);
        }
        float y = a + end_t[kt * 8 + j];
        float mm = y;
        #pragma unroll
        for (int d = 4; d > 0; d >>= 1) mm = fmaxf(mm, __shfl_xor_sync(FULLM, mm, d, 8));
        float q = __expf(y - mm);
        #pragma unroll
        for (int d = 4; d > 0; d >>= 1) q += __shfl_xor_sync(FULLM, q, d, 8);
        float logZ = mm + __logf(q);

        float num = 0.0f;
        for (int t = j; t < TT; t += 8) {
            int tg = labels[b * (3 * TT) + kt * TT + t];
            num += em[t * 8 + tg];
            if (t > 0) {
                int tp = labels[b * (3 * TT) + kt * TT + t - 1];
                num += trans[kt * 64 + tp * 8 + tg];
            } else {
                num += start_t[kt * 8 + tg];
            }
            if (t == TT - 1) num += end_t[kt * 8 + tg];
        }
        #pragma unroll
        for (int d = 4; d > 0; d >>= 1) num += __shfl_xor_sync(FULLM, num, d, 8);

        if (j == 0) atomicAdd(&out[0], logZ - num);
    }
}

// ---------------------------------------------------------------------------
// decode: exact chunked 8-hypothesis backtrace, 2 seqs/block
// ---------------------------------------------------------------------------
__global__ __launch_bounds__(128) void decode_kernel(
    const float* __restrict__ end_t, float* __restrict__ out)
{
    __shared__ unsigned      bp[2][TT];
    __shared__ unsigned char entry[2][64];
    __shared__ unsigned char sel[2][8];

    const int tid   = threadIdx.x;
    const int local = tid >> 6;
    const int lt    = tid & 63;
    const int s     = blockIdx.x * 2 + local;

    for (int i = lt; i < TT; i += 64) bp[local][i] = g_bpw[(size_t)s * TT + i];
    __syncthreads();

    {   // per (chunk, exit hypothesis) backtrace
        const int c = lt >> 3, h = lt & 7;
        const int tb = c * 64 + 1;
        const int te = (c * 64 + 64 < TT) ? c * 64 + 64 : TT - 1;
        int tag = h;
        for (int t = te; t >= tb; t--) tag = (bp[local][t] >> (3 * tag)) & 7;
        entry[local][c * 8 + h] = (unsigned char)tag;
    }
    __syncthreads();

    if (lt == 0) {
        const float* v = g_vscr + ((size_t)s * TT + (TT - 1)) * 8;
        const int kt = s >> 6;
        float best = v[0] + end_t[kt * 8];
        int bi = 0;
        #pragma unroll
        for (int i = 1; i < 8; i++) {
            float cnd = v[i] + end_t[kt * 8 + i];
            if (cnd > best) { best = cnd; bi = i; }
        }
        int ex = bi;
        for (int cc = 7; cc >= 0; cc--) {
            sel[local][cc] = (unsigned char)ex;
            ex = entry[local][cc * 8 + ex];
        }
    }
    __syncthreads();

    if (lt < 8) {
        const int cc = lt;
        const int tb = cc * 64 + 1;
        const int te = (cc * 64 + 64 < TT) ? cc * 64 + 64 : TT - 1;
        int tag = sel[local][cc];
        float* pred = out + PRED_OFF + (size_t)s * TT;
        pred[te] = (float)tag;
        for (int t = te; t >= tb; t--) {
            tag = (bp[local][t] >> (3 * tag)) & 7;
            pred[t - 1] = (float)tag;
        }
    }
}

extern "C" void kernel_launch(void* const* d_in, const int* in_sizes, int n_in,
                              void* d_out, int out_size)
{
    (void)in_sizes; (void)n_in; (void)out_size;
    const float* enc     = (const float*)d_in[0];
    const int*   labels  = (const int*)  d_in[1];
    const float* W       = (const float*)d_in[2];
    const float* bias    = (const float*)d_in[3];
    const float* start_t = (const float*)d_in[4];
    const float* end_t   = (const float*)d_in[5];
    const float* trans   = (const float*)d_in[6];
    float* out = (float*)d_out;

    gemm_kernel<<<128, 128>>>(enc, W, bias, out);
    scan_kernel<<<108, 128>>>(start_t, trans, out);
    post_kernel<<<390, 256>>>(labels, start_t, end_t, trans, out);
    decode_kernel<<<96, 128>>>(end_t, out);
}

// round 4
// speedup vs baseline: 1.9777x; 1.4307x over previous
#include <cuda_runtime.h>

#define BB   64
#define TT   512
#define HH   1024
#define CC   8
#define NROW 32768
#define LOGITS_OFF 1
#define PRED_OFF   (1 + 3*BB*TT*CC)
#define FULLM 0xFFFFFFFFu

// static device scratch
__device__ float         g_expo[3 * NROW * CC];     // exp(logits)
__device__ float         g_fwdP[192 * 8 * 64];      // forward chunk basis matrices
__device__ unsigned char g_bp8 [192 * TT * 8];      // per-(seq,t,state) backpointer
__device__ int           g_last[192];               // final argmax tag per seq

__device__ __forceinline__ void ffma2(unsigned long long& d,
                                      unsigned long long a,
                                      unsigned long long b) {
    asm("fma.rn.f32x2 %0, %1, %2, %0;" : "+l"(d) : "l"(a), "l"(b));
}
__device__ __forceinline__ void cpa16(unsigned sm, const void* g) {
    asm volatile("cp.async.cg.shared.global [%0], [%1], 16;" :: "r"(sm), "l"(g));
}

// ---------------------------------------------------------------------------
// GEMM: M=32768, N=24, K=1024.  256 blocks x 128 threads.
// Block tile: 128 rows x 24 cols. Thread: 8 rows (rgrp+16i) x 3 cols.
// A,W double-buffered k16 tiles via cp.async; f32x2 FMA.
// ---------------------------------------------------------------------------
__global__ __launch_bounds__(128) void gemm_kernel(
    const float* __restrict__ enc, const float* __restrict__ W,
    const float* __restrict__ bias, float* __restrict__ out)
{
    __shared__ float As[2][128 * 20];
    __shared__ float Ws[2][24 * 20];

    const int tid  = threadIdx.x;
    const int rb   = blockIdx.x * 128;
    const int rgrp = tid & 15;
    const int c0   = (tid >> 4) * 3;
    if (blockIdx.x == 0 && tid == 0) out[0] = 0.0f;

    unsigned long long acc[8][3];
    #pragma unroll
    for (int i = 0; i < 8; i++)
        #pragma unroll
        for (int m = 0; m < 3; m++) acc[i][m] = 0ull;

    unsigned asB[2] = { (unsigned)__cvta_generic_to_shared(&As[0][0]),
                        (unsigned)__cvta_generic_to_shared(&As[1][0]) };
    unsigned wsB[2] = { (unsigned)__cvta_generic_to_shared(&Ws[0][0]),
                        (unsigned)__cvta_generic_to_shared(&Ws[1][0]) };

    auto load_tiles = [&](int kb, int bf) {
        #pragma unroll
        for (int i = 0; i < 4; i++) {
            int idx = tid + i * 128;
            int row = idx >> 2, q = idx & 3;
            cpa16(asB[bf] + (row * 20 + q * 4) * 4,
                  enc + (size_t)(rb + row) * HH + kb + q * 4);
        }
        if (tid < 96) {
            int c = tid >> 2, q = tid & 3;
            cpa16(wsB[bf] + (c * 20 + q * 4) * 4, W + (size_t)c * HH + kb + q * 4);
        }
        asm volatile("cp.async.commit_group;");
    };

    load_tiles(0, 0);
    int buf = 0;
    for (int kb = 0; kb < HH; kb += 16, buf ^= 1) {
        if (kb + 16 < HH) {
            load_tiles(kb + 16, buf ^ 1);
            asm volatile("cp.async.wait_group 1;");
        } else {
            asm volatile("cp.async.wait_group 0;");
        }
        __syncthreads();
        #pragma unroll
        for (int k4 = 0; k4 < 16; k4 += 4) {
            ulonglong2 wv[3];
            #pragma unroll
            for (int m = 0; m < 3; m++)
                wv[m] = *reinterpret_cast<const ulonglong2*>(&Ws[buf][(c0 + m) * 20 + k4]);
            #pragma unroll
            for (int i = 0; i < 8; i++) {
                int r = rgrp + 16 * i;
                ulonglong2 av = *reinterpret_cast<const ulonglong2*>(&As[buf][r * 20 + k4]);
                #pragma unroll
                for (int m = 0; m < 3; m++) {
                    ffma2(acc[i][m], av.x, wv[m].x);
                    ffma2(acc[i][m], av.y, wv[m].y);
                }
            }
        }
        __syncthreads();
    }

    #pragma unroll
    for (int i = 0; i < 8; i++) {
        const int r = rb + rgrp + 16 * i;
        #pragma unroll
        for (int m = 0; m < 3; m++) {
            int col = c0 + m;
            int kt = col >> 3, cc = col & 7;
            float2 f = *reinterpret_cast<float2*>(&acc[i][m]);
            float val = f.x + f.y + bias[col];
            size_t base = ((size_t)kt * NROW + r) * 8 + cc;
            out[LOGITS_OFF + base] = val;
            g_expo[base] = __expf(val);
        }
    }
}

// ---------------------------------------------------------------------------
// scan: blocks 0..11  = exact Viterbi v-scan, bp bytes stored inline
//       blocks 12..107 = forward chunk basis matrices (linear domain)
// ---------------------------------------------------------------------------
__global__ __launch_bounds__(128) void scan_kernel(
    const float* __restrict__ start_t, const float* __restrict__ end_t,
    const float* __restrict__ trans, const float* __restrict__ out)
{
    const int tid = threadIdx.x;

    if (blockIdx.x < 12) {
        const int g  = blockIdx.x * 16 + (tid >> 3);   // seq 0..191
        const int j  = tid & 7;
        const int kt = g >> 6;
        const float* em = out + LOGITS_OFF + (size_t)g * (TT * CC);
        unsigned char* bp = g_bp8 + (size_t)g * (TT * 8);

        float tr[8];
        #pragma unroll
        for (int i = 0; i < 8; i++) tr[i] = trans[kt * 64 + i * 8 + j];

        float v = start_t[kt * 8 + j] + em[j];

        float eb[8];
        #pragma unroll
        for (int u = 0; u < 8; u++) eb[u] = em[(1 + u) * 8 + j];

        for (int tw = 1; tw < TT; tw += 8) {
            float nb[8];
            #pragma unroll
            for (int u = 0; u < 8; u++) {
                int tn = tw + 8 + u;
                nb[u] = (tn < TT) ? em[tn * 8 + j] : 0.0f;
            }
            #pragma unroll
            for (int u = 0; u < 8; u++) {
                int t = tw + u;
                if (t < TT) {
                    float c0 = __shfl_sync(FULLM, v, 0, 8) + tr[0];
                    float c1 = __shfl_sync(FULLM, v, 1, 8) + tr[1];
                    float c2 = __shfl_sync(FULLM, v, 2, 8) + tr[2];
                    float c3 = __shfl_sync(FULLM, v, 3, 8) + tr[3];
                    float c4 = __shfl_sync(FULLM, v, 4, 8) + tr[4];
                    float c5 = __shfl_sync(FULLM, v, 5, 8) + tr[5];
                    float c6 = __shfl_sync(FULLM, v, 6, 8) + tr[6];
                    float c7 = __shfl_sync(FULLM, v, 7, 8) + tr[7];
                    float m = fmaxf(fmaxf(fmaxf(c0, c1), fmaxf(c2, c3)),
                                    fmaxf(fmaxf(c4, c5), fmaxf(c6, c7)));
                    // first-occurrence argmax (off critical path)
                    unsigned mk = (c0 == m) ? 1u : 0u;
                    mk |= (c1 == m) ? 2u : 0u;
                    mk |= (c2 == m) ? 4u : 0u;
                    mk |= (c3 == m) ? 8u : 0u;
                    mk |= (c4 == m) ? 16u : 0u;
                    mk |= (c5 == m) ? 32u : 0u;
                    mk |= (c6 == m) ? 64u : 0u;
                    mk |= (c7 == m) ? 128u : 0u;
                    bp[t * 8 + j] = (unsigned char)(__ffs(mk) - 1);
                    v = m + eb[u];
                }
            }
            #pragma unroll
            for (int u = 0; u < 8; u++) eb[u] = nb[u];
        }

        // final argmax (first occurrence) over states
        float y = v + end_t[kt * 8 + j];
        float gg[8];
        #pragma unroll
        for (int i = 0; i < 8; i++) gg[i] = __shfl_sync(FULLM, y, i, 8);
        float bv = gg[0]; int last = 0;
        #pragma unroll
        for (int i = 1; i < 8; i++) { if (gg[i] > bv) { bv = gg[i]; last = i; } }
        if (j == 0) g_last[g] = last;
    } else {
        // thread = (seq s, chunk c, basis row ib)
        const int flat = (blockIdx.x - 12) * 128 + tid;
        const int ib = flat & 7;
        const int c  = (flat >> 3) & 7;
        const int s  = flat >> 6;
        const int kt = s >> 6;

        float ec[64];
        #pragma unroll
        for (int i = 0; i < 64; i++) ec[i] = __expf(trans[kt * 64 + i]) * 0.125f;

        float P[8];
        #pragma unroll
        for (int jj = 0; jj < 8; jj++) P[jj] = (jj == ib) ? 1.0f : 0.0f;

        const int tb = c * 64 + 1;
        const int te = (c * 64 + 64 < TT) ? c * 64 + 64 : TT - 1;
        const float* eo = g_expo + (size_t)s * (TT * CC);

        float4 pa0 = *reinterpret_cast<const float4*>(eo + tb * 8);
        float4 pb0 = *reinterpret_cast<const float4*>(eo + tb * 8 + 4);
        float4 pa1 = *reinterpret_cast<const float4*>(eo + (tb + 1) * 8);
        float4 pb1 = *reinterpret_cast<const float4*>(eo + (tb + 1) * 8 + 4);

        for (int t = tb; t <= te; t++) {
            float4 ca = pa0, cb = pb0;
            pa0 = pa1; pb0 = pb1;
            int tn = t + 2;
            if (tn <= te) {
                pa1 = *reinterpret_cast<const float4*>(eo + tn * 8);
                pb1 = *reinterpret_cast<const float4*>(eo + tn * 8 + 4);
            }
            float np[8];
            #pragma unroll
            for (int jj = 0; jj < 8; jj++) {
                float sum = P[0] * ec[jj];
                #pragma unroll
                for (int i = 1; i < 8; i++) sum = fmaf(P[i], ec[i * 8 + jj], sum);
                np[jj] = sum;
            }
            P[0] = np[0] * ca.x; P[1] = np[1] * ca.y;
            P[2] = np[2] * ca.z; P[3] = np[3] * ca.w;
            P[4] = np[4] * cb.x; P[5] = np[5] * cb.y;
            P[6] = np[6] * cb.z; P[7] = np[7] * cb.w;
        }
        float* dst = g_fwdP + ((size_t)(s * 8 + c) * 8 + ib) * 8;
        *reinterpret_cast<float4*>(dst)     = make_float4(P[0], P[1], P[2], P[3]);
        *reinterpret_cast<float4*>(dst + 4) = make_float4(P[4], P[5], P[6], P[7]);
    }
}

// ---------------------------------------------------------------------------
// final: blocks 0..47 = decode (4 seqs/block); blocks 48..53 = loss
// ---------------------------------------------------------------------------
__global__ __launch_bounds__(256) void final_kernel(
    const int* __restrict__ labels, const float* __restrict__ start_t,
    const float* __restrict__ end_t, const float* __restrict__ trans,
    float* __restrict__ out)
{
    const int tid = threadIdx.x;

    if (blockIdx.x < 48) {
        __shared__ unsigned char bpS[4][TT * 8];
        __shared__ unsigned char entry[4][64];
        __shared__ unsigned char sel[4][8];

        const int local = tid >> 6;
        const int lt    = tid & 63;
        const int s     = blockIdx.x * 4 + local;

        {   // load 4KB of bp bytes per sequence
            const float4* src = reinterpret_cast<const float4*>(g_bp8 + (size_t)s * (TT * 8));
            float4* dst = reinterpret_cast<float4*>(&bpS[local][0]);
            #pragma unroll
            for (int i = 0; i < 4; i++) dst[lt + 64 * i] = src[lt + 64 * i];
        }
        __syncthreads();

        {   // per (chunk, exit hypothesis) backtrace
            const int c = lt >> 3, h = lt & 7;
            const int tb = c * 64 + 1;
            const int te = (c * 64 + 64 < TT) ? c * 64 + 64 : TT - 1;
            int tag = h;
            for (int t = te; t >= tb; t--) tag = bpS[local][t * 8 + tag];
            entry[local][c * 8 + h] = (unsigned char)tag;
        }
        __syncthreads();

        if (lt == 0) {
            int ex = g_last[s];
            for (int cc = 7; cc >= 0; cc--) {
                sel[local][cc] = (unsigned char)ex;
                ex = entry[local][cc * 8 + ex];
            }
        }
        __syncthreads();

        if (lt < 8) {
            const int cc = lt;
            const int tb = cc * 64 + 1;
            const int te = (cc * 64 + 64 < TT) ? cc * 64 + 64 : TT - 1;
            int tag = sel[local][cc];
            float* pred = out + PRED_OFF + (size_t)s * TT;
            pred[te] = (float)tag;
            for (int t = te; t >= tb; t--) {
                tag = bpS[local][t * 8 + tag];
                pred[t - 1] = (float)tag;
            }
        }
    } else {
        const int g  = (blockIdx.x - 48) * 32 + (tid >> 3);   // seq 0..191
        const int j  = tid & 7;
        const int kt = g >> 6, b = g & 63;
        const float* em = out + LOGITS_OFF + (size_t)g * (TT * CC);
        const float LOG8 = 2.0794415416798357f;

        float a = start_t[kt * 8 + j] + em[j];
        for (int c = 0; c < 8; c++) {
            float n = (c < 7) ? 64.0f : 63.0f;
            const float* Pp = g_fwdP + (size_t)(g * 8 + c) * 64;
            float lm[8];
            #pragma unroll
            for (int i = 0; i < 8; i++)
                lm[i] = __logf(Pp[i * 8 + j]) + n * LOG8 + __shfl_sync(FULLM, a, i, 8);
            float m = fmaxf(fmaxf(fmaxf(lm[0], lm[1]), fmaxf(lm[2], lm[3])),
                            fmaxf(fmaxf(lm[4], lm[5]), fmaxf(lm[6], lm[7])));
            float ssum = 0.0f;
            #pragma unroll
            for (int i = 0; i < 8; i++) ssum += __expf(lm[i] - m);
            a = m + __logf(ssum);
        }
        float y = a + end_t[kt * 8 + j];
        float mm = y;
        #pragma unroll
        for (int d = 4; d > 0; d >>= 1) mm = fmaxf(mm, __shfl_xor_sync(FULLM, mm, d, 8));
        float q = __expf(y - mm);
        #pragma unroll
        for (int d = 4; d > 0; d >>= 1) q += __shfl_xor_sync(FULLM, q, d, 8);
        float logZ = mm + __logf(q);

        float num = 0.0f;
        for (int t = j; t < TT; t += 8) {
            int tg = labels[b * (3 * TT) + kt * TT + t];
            num += em[t * 8 + tg];
            if (t > 0) {
                int tp = labels[b * (3 * TT) + kt * TT + t - 1];
                num += trans[kt * 64 + tp * 8 + tg];
            } else {
                num += start_t[kt * 8 + tg];
            }
            if (t == TT - 1) num += end_t[kt * 8 + tg];
        }
        #pragma unroll
        for (int d = 4; d > 0; d >>= 1) num += __shfl_xor_sync(FULLM, num, d, 8);

        if (j == 0) atomicAdd(&out[0], logZ - num);
    }
}

extern "C" void kernel_launch(void* const* d_in, const int* in_sizes, int n_in,
                              void* d_out, int out_size)
{
    (void)in_sizes; (void)n_in; (void)out_size;
    const float* enc     = (const float*)d_in[0];
    const int*   labels  = (const int*)  d_in[1];
    const float* W       = (const float*)d_in[2];
    const float* bias    = (const float*)d_in[3];
    const float* start_t = (const float*)d_in[4];
    const float* end_t   = (const float*)d_in[5];
    const float* trans   = (const float*)d_in[6];
    float* out = (float*)d_out;

    gemm_kernel <<<256, 128>>>(enc, W, bias, out);
    scan_kernel <<<108, 128>>>(start_t, end_t, trans, out);
    final_kernel<<<54, 256>>>(labels, start_t, end_t, trans, out);
}